// round 2
// baseline (speedup 1.0000x reference)
#include <cuda_runtime.h>

// Problem constants
#define BB    256
#define HH    512
#define G4    2048
#define SRCT  512
#define INP   64
#define TGTT  96

// Kernel config
#define NBLK  128
#define NTHR  512
#define KC    32

// ---------------- device globals (scratch; no allocations allowed) ----------
static __device__ __align__(16) float g_h[2][2][BB * HH];   // [layer][parity][b*H+u]
static __device__ __align__(16) float g_c[2][BB * HH];      // [layer][b*H+u]
static __device__ __align__(16) float g_x[BB];              // decoder scalar input
static __device__ __align__(16) float g_fc[BB * HH];        // fc hidden
static __device__ __align__(16) float g_part[3 * BB * G4];  // split-K partials
static __device__ int g_flag[NBLK];
static __device__ unsigned g_count;
static __device__ volatile unsigned g_sense;

struct SM {
    float hs[KC][128];
    float ws[KC][128];
};

// ---------------- helpers ---------------------------------------------------
__device__ __forceinline__ float sigm(float x) {
    return 1.0f / (1.0f + __expf(-x));
}
__device__ __forceinline__ float tanh_f(float x) {
    return 2.0f / (1.0f + __expf(-2.0f * x)) - 1.0f;
}

// grid-wide barrier: monotonic generation counter (reset by prologue kernel)
__device__ __forceinline__ void gsync() {
    __threadfence();
    __syncthreads();
    if (threadIdx.x == 0) {
        unsigned a = atomicAdd(&g_count, 1u);
        unsigned target = a / NBLK + 1u;
        if ((a % NBLK) == (NBLK - 1)) {
            __threadfence();
            g_sense = target;
        } else {
            while (g_sense < target) { __nanosleep(64); }
        }
        __threadfence();
    }
    __syncthreads();
}

template <bool CG, bool RELU>
__device__ __forceinline__ void ldx8(float* r, const float* p) {
    float4 a, b;
    if (CG) {
        a = __ldcg((const float4*)p);
        b = __ldcg(((const float4*)p) + 1);
    } else {
        a = __ldg((const float4*)p);
        b = __ldg(((const float4*)p) + 1);
    }
    if (RELU) {
        a.x = fmaxf(a.x, 0.f); a.y = fmaxf(a.y, 0.f);
        a.z = fmaxf(a.z, 0.f); a.w = fmaxf(a.w, 0.f);
        b.x = fmaxf(b.x, 0.f); b.y = fmaxf(b.y, 0.f);
        b.z = fmaxf(b.z, 0.f); b.w = fmaxf(b.w, 0.f);
    }
    r[0] = a.x; r[1] = a.y; r[2] = a.z; r[3] = a.w;
    r[4] = b.x; r[5] = b.y; r[6] = b.z; r[7] = b.w;
}

__device__ __forceinline__ void ldw8(float* r, const float* p) {
    float4 a = __ldg((const float4*)p);
    float4 b = __ldg(((const float4*)p) + 1);
    r[0] = a.x; r[1] = a.y; r[2] = a.z; r[3] = a.w;
    r[4] = b.x; r[5] = b.y; r[6] = b.z; r[7] = b.w;
}

__device__ __forceinline__ void fma8(float* a8, float av,
                                     const float4& w0, const float4& w1) {
    a8[0] += av * w0.x; a8[1] += av * w0.y; a8[2] += av * w0.z; a8[3] += av * w0.w;
    a8[4] += av * w1.x; a8[5] += av * w1.y; a8[6] += av * w1.z; a8[7] += av * w1.w;
}

// Accumulate acc[4 b-rows][8 cols] += X_tile * W_tile^T over nt k-tiles.
// Block tile 128 rows x 128 cols; 512 threads; thread tile 4x8.
// px: this thread's loader pointer into X (row b_base+lrow, col k0+kofs).
// pw: this thread's loader pointer into W (row for panel col lrow, col k0+kofs).
template <bool CG, bool RELU>
__device__ __forceinline__ void mm_accum(float (&acc)[4][8], SM& sm,
                                         const float* px, const float* pw,
                                         int nt, int tx, int ty,
                                         int lrow, int kofs) {
    float rx[8], rw[8];
    ldx8<CG, RELU>(rx, px);
    ldw8(rw, pw);
    for (int kt = 0; kt < nt; kt++) {
        __syncthreads();
#pragma unroll
        for (int i = 0; i < 8; i++) {
            sm.hs[kofs + i][lrow] = rx[i];
            sm.ws[kofs + i][lrow] = rw[i];
        }
        __syncthreads();
        if (kt + 1 < nt) {
            ldx8<CG, RELU>(rx, px + (kt + 1) * KC);
            ldw8(rw, pw + (kt + 1) * KC);
        }
        const float4* h4 = reinterpret_cast<const float4*>(&sm.hs[0][0]);
        const float4* w4 = reinterpret_cast<const float4*>(&sm.ws[0][0]);
#pragma unroll
        for (int kk = 0; kk < KC; kk++) {
            float4 a  = h4[kk * 32 + ty];
            float4 w0 = w4[kk * 32 + tx * 2];
            float4 w1 = w4[kk * 32 + tx * 2 + 1];
            fma8(acc[0], a.x, w0, w1);
            fma8(acc[1], a.y, w0, w1);
            fma8(acc[2], a.z, w0, w1);
            fma8(acc[3], a.w, w0, w1);
        }
    }
}

// writer side of split-K: store partial + raise flag
__device__ __forceinline__ void store_partial(const float (&acc)[4][8],
                                              long rowstride, int b_base, int jb,
                                              int ks, int ty, int tx,
                                              int tid, int seq) {
    float* pp = g_part + (long)(ks - 1) * (BB * G4);
#pragma unroll
    for (int i = 0; i < 4; i++) {
        long o = (long)(b_base + ty * 4 + i) * rowstride + jb + tx * 8;
        __stcg((float4*)(pp + o), make_float4(acc[i][0], acc[i][1], acc[i][2], acc[i][3]));
        __stcg((float4*)(pp + o + 4), make_float4(acc[i][4], acc[i][5], acc[i][6], acc[i][7]));
    }
    __syncthreads();
    if (tid == 0) {
        __threadfence();
        ((volatile int*)g_flag)[blockIdx.x] = seq;
    }
}

// reader side: wait for nw partner flags, then add their partials into acc
__device__ __forceinline__ void combine_partials(float (&acc)[4][8],
                                                 long rowstride, int b_base, int jb,
                                                 int nw, int ty, int tx,
                                                 int tid, int seq) {
    if (tid == 0) {
        int base = blockIdx.x;
        for (int s = 1; s <= nw; s++) {
            while (((volatile int*)g_flag)[base + s] < seq) { __nanosleep(32); }
        }
    }
    __syncthreads();
    __threadfence();
#pragma unroll
    for (int i = 0; i < 4; i++) {
        long o = (long)(b_base + ty * 4 + i) * rowstride + jb + tx * 8;
#pragma unroll
        for (int s = 0; s < 3; s++) {
            if (s < nw) {
                const float* pp = g_part + (long)s * (BB * G4);
                float4 q0 = __ldcg((const float4*)(pp + o));
                float4 q1 = __ldcg((const float4*)(pp + o + 4));
                acc[i][0] += q0.x; acc[i][1] += q0.y; acc[i][2] += q0.z; acc[i][3] += q0.w;
                acc[i][4] += q1.x; acc[i][5] += q1.y; acc[i][6] += q1.z; acc[i][7] += q1.w;
            }
        }
    }
}

// One LSTM layer step. Block tile: 128 b-rows x 32 cells x 4 gates, split-K-4.
// Kx: 64 (encoder L0 input), 512 (h input), 1 (decoder scalar), 0 (none).
__device__ __forceinline__ void lstm_layer(SM& sm,
                                           const float* xbase, long xld,
                                           int Kx, bool xcg,
                                           const float* Wih, const float* Whh,
                                           const float* bih, const float* bhh,
                                           const float* hprev, float* cbuf,
                                           float* hnext,
                                           int b_base, int jb, int u_base, int ks,
                                           int seq, int tx, int ty,
                                           int lrow, int kofs, int tid) {
    float acc[4][8];
    const int u0 = u_base + tx * 2;

    if (ks == 0) {
#pragma unroll
        for (int q = 0; q < 8; q++) {
            int g = q & 3, uo = q >> 2;
            float bb = __ldg(bih + g * HH + u0 + uo) + __ldg(bhh + g * HH + u0 + uo);
            acc[0][q] = bb; acc[1][q] = bb; acc[2][q] = bb; acc[3][q] = bb;
        }
    } else {
#pragma unroll
        for (int q = 0; q < 8; q++) {
            acc[0][q] = 0.f; acc[1][q] = 0.f; acc[2][q] = 0.f; acc[3][q] = 0.f;
        }
    }

    const int wg = lrow & 3;                 // gate of this panel column
    const int wu = u_base + (lrow >> 2);     // cell of this panel column

    // ---- input GEMM ----
    if (Kx >= 64) {
        const int nsplit = (Kx == 64) ? 2 : 4;
        const int xper = Kx / nsplit;        // 32 or 128
        if (ks < nsplit) {
            const int k0 = ks * xper;
            const float* px = xbase + (long)(b_base + lrow) * xld + k0 + kofs;
            const float* pw = Wih + (long)(wg * HH + wu) * Kx + k0 + kofs;
            if (xcg) mm_accum<true, false>(acc, sm, px, pw, xper / KC, tx, ty, lrow, kofs);
            else     mm_accum<false, false>(acc, sm, px, pw, xper / KC, tx, ty, lrow, kofs);
        }
    } else if (Kx == 1 && ks == 0) {
        float wv[8];
#pragma unroll
        for (int q = 0; q < 8; q++) {
            int g = q & 3, uo = q >> 2;
            wv[q] = __ldg(Wih + g * HH + u0 + uo);
        }
#pragma unroll
        for (int i = 0; i < 4; i++) {
            float xv = __ldcg(&g_x[b_base + ty * 4 + i]);
#pragma unroll
            for (int q = 0; q < 8; q++) acc[i][q] += xv * wv[q];
        }
    }

    // ---- recurrent GEMM (K = 512, split 4 ways) ----
    {
        const int k0 = ks * (HH / 4);
        const float* px = hprev + (long)(b_base + lrow) * HH + k0 + kofs;
        const float* pw = Whh + (long)(wg * HH + wu) * HH + k0 + kofs;
        mm_accum<true, false>(acc, sm, px, pw, (HH / 4) / KC, tx, ty, lrow, kofs);
    }

    if (ks != 0) {
        store_partial(acc, G4, b_base, jb, ks, ty, tx, tid, seq);
        return;
    }

    combine_partials(acc, G4, b_base, jb, 3, ty, tx, tid, seq);

    // ---- activation + state update (2 cells per thread) ----
#pragma unroll
    for (int i = 0; i < 4; i++) {
        const int b = b_base + ty * 4 + i;
        const long co = (long)b * HH + u0;
        float i0 = sigm(acc[i][0]), f0 = sigm(acc[i][1]);
        float g0 = tanh_f(acc[i][2]), o0 = sigm(acc[i][3]);
        float i1 = sigm(acc[i][4]), f1 = sigm(acc[i][5]);
        float g1 = tanh_f(acc[i][6]), o1 = sigm(acc[i][7]);
        float2 cc = __ldcg((const float2*)(cbuf + co));
        float c0 = f0 * cc.x + i0 * g0;
        float c1 = f1 * cc.y + i1 * g1;
        __stcg((float2*)(cbuf + co), make_float2(c0, c1));
        __stcg((float2*)(hnext + co), make_float2(o0 * tanh_f(c0), o1 * tanh_f(c1)));
    }
}

// ---------------- prologue: reset barrier + states --------------------------
__global__ void reset_kernel(const float* __restrict__ tgt) {
    long idx = (long)blockIdx.x * blockDim.x + threadIdx.x;
    long stride = (long)gridDim.x * blockDim.x;
    float* hp = &g_h[0][0][0];
    for (long i = idx; i < 2L * 2 * BB * HH; i += stride) hp[i] = 0.f;
    float* cp = &g_c[0][0];
    for (long i = idx; i < 2L * BB * HH; i += stride) cp[i] = 0.f;
    if (idx < BB) g_x[idx] = tgt[idx * TGTT];  // tgt[:,0]
    if (idx < NBLK) g_flag[idx] = 0;
    if (idx == 0) { g_count = 0u; g_sense = 0u; }
}

// ---------------- main persistent kernel ------------------------------------
__global__ __launch_bounds__(NTHR, 1) void seq2seq_kernel(
    const float* __restrict__ src, const float* __restrict__ tgt,
    const float* __restrict__ eWih0, const float* __restrict__ eWhh0,
    const float* __restrict__ ebih0, const float* __restrict__ ebhh0,
    const float* __restrict__ dWih0, const float* __restrict__ dWhh0,
    const float* __restrict__ dbih0, const float* __restrict__ dbhh0,
    const float* __restrict__ eWih1, const float* __restrict__ eWhh1,
    const float* __restrict__ ebih1, const float* __restrict__ ebhh1,
    const float* __restrict__ dWih1, const float* __restrict__ dWhh1,
    const float* __restrict__ dbih1, const float* __restrict__ dbhh1,
    const float* __restrict__ fW0, const float* __restrict__ fb0,
    const float* __restrict__ fW1, const float* __restrict__ fb1,
    float* __restrict__ out) {
    __shared__ SM sm;

    const int tid = threadIdx.x;
    const int tx = tid & 15;          // 8 output cols (2 cells x 4 gates)
    const int ty = tid >> 4;          // 4 output rows
    const int lrow = tid & 127;       // loader: panel column / x row
    const int kofs = (tid >> 7) * 8;  // loader: k offset within KC

    const int tile = blockIdx.x >> 2;     // 0..31
    const int ks = blockIdx.x & 3;        // split-K id
    const int b_base = (tile >> 4) * 128; // 0 or 128
    const int jb = (tile & 15) * 128;     // gate-col base
    const int u_base = jb >> 2;           // cell base (32 cells per tile)

    int par = 0;
    int seq = 0;

    // ---------------- encoder ----------------
    for (int t = 0; t < SRCT; t++) {
        seq++;
        lstm_layer(sm, src + (long)t * INP, (long)SRCT * INP, INP, false,
                   eWih0, eWhh0, ebih0, ebhh0,
                   g_h[0][par], g_c[0], g_h[0][par ^ 1],
                   b_base, jb, u_base, ks, seq, tx, ty, lrow, kofs, tid);
        gsync();
        seq++;
        lstm_layer(sm, g_h[0][par ^ 1], HH, HH, true,
                   eWih1, eWhh1, ebih1, ebhh1,
                   g_h[1][par], g_c[1], g_h[1][par ^ 1],
                   b_base, jb, u_base, ks, seq, tx, ty, lrow, kofs, tid);
        gsync();
        par ^= 1;
    }

    // ---------------- decoder ----------------
    for (int t = 0; t < TGTT; t++) {
        seq++;
        lstm_layer(sm, nullptr, 0, 1, true,
                   dWih0, dWhh0, dbih0, dbhh0,
                   g_h[0][par], g_c[0], g_h[0][par ^ 1],
                   b_base, jb, u_base, ks, seq, tx, ty, lrow, kofs, tid);
        gsync();
        seq++;
        lstm_layer(sm, g_h[0][par ^ 1], HH, HH, true,
                   dWih1, dWhh1, dbih1, dbhh1,
                   g_h[1][par], g_c[1], g_h[1][par ^ 1],
                   b_base, jb, u_base, ks, seq, tx, ty, lrow, kofs, tid);
        gsync();

        // fc0: g_fc = relu( relu(h1) @ W0^T + b0 ). 8 tiles x split-K-4 = 32 blocks.
        seq++;
        if (blockIdx.x < 32) {
            const int ftile = blockIdx.x >> 2;      // 0..7
            const int fks = blockIdx.x & 3;
            const int fb_base = (ftile >> 2) * 128; // 0 or 128
            const int fjb = (ftile & 3) * 128;      // col base within 512
            float acc[4][8];
            if (fks == 0) {
#pragma unroll
                for (int q = 0; q < 8; q++) {
                    float bb = __ldg(fb0 + fjb + tx * 8 + q);
                    acc[0][q] = bb; acc[1][q] = bb; acc[2][q] = bb; acc[3][q] = bb;
                }
            } else {
#pragma unroll
                for (int q = 0; q < 8; q++) {
                    acc[0][q] = 0.f; acc[1][q] = 0.f; acc[2][q] = 0.f; acc[3][q] = 0.f;
                }
            }
            const int k0 = fks * (HH / 4);
            const float* px = g_h[1][par ^ 1] + (long)(fb_base + lrow) * HH + k0 + kofs;
            const float* pw = fW0 + (long)(fjb + lrow) * HH + k0 + kofs;
            mm_accum<true, true>(acc, sm, px, pw, (HH / 4) / KC, tx, ty, lrow, kofs);

            if (fks != 0) {
                store_partial(acc, HH, fb_base, fjb, fks, ty, tx, tid, seq);
            } else {
                combine_partials(acc, HH, fb_base, fjb, 3, ty, tx, tid, seq);
#pragma unroll
                for (int i = 0; i < 4; i++) {
                    const int b = fb_base + ty * 4 + i;
                    const long o = (long)b * HH + fjb + tx * 8;
                    __stcg((float4*)(g_fc + o),
                           make_float4(fmaxf(acc[i][0], 0.f), fmaxf(acc[i][1], 0.f),
                                       fmaxf(acc[i][2], 0.f), fmaxf(acc[i][3], 0.f)));
                    __stcg((float4*)(g_fc + o + 4),
                           make_float4(fmaxf(acc[i][4], 0.f), fmaxf(acc[i][5], 0.f),
                                       fmaxf(acc[i][6], 0.f), fmaxf(acc[i][7], 0.f)));
                }
            }
        }
        gsync();

        // fc1: out[b] = g_fc[b] . W1 + b1 ; becomes next decoder input
        if (blockIdx.x == 0 && tid < BB) {
            const int b = tid;
            const float4* tp = (const float4*)(g_fc + (long)b * HH);
            const float4* wp = (const float4*)fW1;
            float s0 = 0.f, s1 = 0.f, s2 = 0.f, s3 = 0.f;
#pragma unroll 8
            for (int k = 0; k < HH / 4; k++) {
                float4 v = __ldcg(tp + k);
                float4 w = __ldg(wp + k);
                s0 += v.x * w.x; s1 += v.y * w.y;
                s2 += v.z * w.z; s3 += v.w * w.w;
            }
            float o = (s0 + s1) + (s2 + s3) + __ldg(fb1);
            out[(long)b * TGTT + t] = o;
            __stcg(&g_x[b], o);
        }
        gsync();
        par ^= 1;
    }
}

// ---------------- launch ----------------------------------------------------
extern "C" void kernel_launch(void* const* d_in, const int* in_sizes, int n_in,
                              void* d_out, int out_size) {
    const float* src   = (const float*)d_in[0];
    const float* tgt   = (const float*)d_in[1];
    const float* eWih0 = (const float*)d_in[2];
    const float* eWhh0 = (const float*)d_in[3];
    const float* ebih0 = (const float*)d_in[4];
    const float* ebhh0 = (const float*)d_in[5];
    const float* dWih0 = (const float*)d_in[6];
    const float* dWhh0 = (const float*)d_in[7];
    const float* dbih0 = (const float*)d_in[8];
    const float* dbhh0 = (const float*)d_in[9];
    const float* eWih1 = (const float*)d_in[10];
    const float* eWhh1 = (const float*)d_in[11];
    const float* ebih1 = (const float*)d_in[12];
    const float* ebhh1 = (const float*)d_in[13];
    const float* dWih1 = (const float*)d_in[14];
    const float* dWhh1 = (const float*)d_in[15];
    const float* dbih1 = (const float*)d_in[16];
    const float* dbhh1 = (const float*)d_in[17];
    const float* fW0   = (const float*)d_in[18];
    const float* fb0   = (const float*)d_in[19];
    const float* fW1   = (const float*)d_in[20];
    const float* fb1   = (const float*)d_in[21];
    float* out = (float*)d_out;

    reset_kernel<<<512, 256>>>(tgt);
    seq2seq_kernel<<<NBLK, NTHR>>>(src, tgt,
                                   eWih0, eWhh0, ebih0, ebhh0,
                                   dWih0, dWhh0, dbih0, dbhh0,
                                   eWih1, eWhh1, ebih1, ebhh1,
                                   dWih1, dWhh1, dbih1, dbhh1,
                                   fW0, fb0, fW1, fb1, out);
}